// round 1
// baseline (speedup 1.0000x reference)
#include <cuda_runtime.h>

#define TT  64
#define BB  128
#define NS  64
#define NC  32
#define NSC 96
#define NTH 512

#define SV_STRIDE 68   // 64 + 4 pad, keeps float4 alignment
#define SW_STRIDE 100  // 96 + 4 pad, float4-aligned, 4-way-conflict transpose read (cheap)
#define SK_STRIDE 68

// Scratch for gains produced by backward pass, consumed by forward pass.
__device__ float g_K[TT * BB * NC * NS];   // [t][b][m][i]
__device__ float g_k[TT * BB * NC];        // [t][b][m]

static __global__ void __launch_bounds__(NTH, 1)
lqr_kernel(const float* __restrict__ gC, const float* __restrict__ gc,
           const float* __restrict__ gF, const float* __restrict__ gf,
           const float* __restrict__ gx0, float* __restrict__ gout)
{
    extern __shared__ float sm[];
    float* sV    = sm;                      // 64*68  = 4352
    float* sF    = sV + NS * SV_STRIDE;     // 64*96  = 6144
    float* sW    = sF + NS * NSC;           // 64*100 = 6400
    float* sQ    = sW + NS * SW_STRIDE;     // 96*96  = 9216
    float* sL    = sQ + NSC * NSC;          // 32*33  = 1056
    float* sLinv = sL + NC * 33;            // 32
    float* sK    = sLinv + NC;              // 32*68  = 2176
    float* sq    = sK + NC * SK_STRIDE;     // 96
    float* sv    = sq + NSC;                // 64
    float* sh    = sv + NS;                 // 64
    float* sf    = sh + NS;                 // 64
    float* sk    = sf + NS;                 // 32
    float* sx    = sk + NC;                 // 64
    float* stau  = sx + NS;                 // 96

    const int tid  = threadIdx.x;
    const int b    = blockIdx.x;
    const int lane = tid & 31;
    const int warp = tid >> 5;

    // V = 0, v = 0
    for (int i = tid; i < NS * SV_STRIDE; i += NTH) sV[i] = 0.0f;
    if (tid < NS) sv[tid] = 0.0f;
    __syncthreads();

    // ================= Backward Riccati pass =================
    for (int t = TT - 1; t >= 0; --t) {
        const long base = (long)(t * BB + b);

        // Load C_t -> sQ (Q starts as C), F_t -> sF, c_t -> sq, f_t -> sf
        {
            const float4* Cg = (const float4*)(gC + base * (long)(NSC * NSC));
            float4* Qd = (float4*)sQ;
            for (int i = tid; i < (NSC * NSC) / 4; i += NTH) Qd[i] = Cg[i];
            const float4* Fg = (const float4*)(gF + base * (long)(NS * NSC));
            float4* Fd = (float4*)sF;
            for (int i = tid; i < (NS * NSC) / 4; i += NTH) Fd[i] = Fg[i];
            if (tid < NSC) sq[tid] = gc[base * NSC + tid];
            if (tid < NS)  sf[tid] = gf[base * NS + tid];
        }
        __syncthreads();

        // ---- W = V @ F (V symmetric: V[i][k] = sV[k*stride+i]) ; h = v + V f ----
        if (tid < 384) {
            const int tj = tid % 24, ti = tid / 24;
            const int i0 = ti * 4, j0 = tj * 4;
            float acc[4][4];
            #pragma unroll
            for (int r = 0; r < 4; r++)
                #pragma unroll
                for (int cc = 0; cc < 4; cc++) acc[r][cc] = 0.0f;
            #pragma unroll 2
            for (int k = 0; k < NS; k++) {
                const float4 av = *(const float4*)(sV + k * SV_STRIDE + i0);
                const float4 bv = *(const float4*)(sF + k * NSC + j0);
                const float aa[4] = {av.x, av.y, av.z, av.w};
                const float bb[4] = {bv.x, bv.y, bv.z, bv.w};
                #pragma unroll
                for (int r = 0; r < 4; r++)
                    #pragma unroll
                    for (int cc = 0; cc < 4; cc++) acc[r][cc] += aa[r] * bb[cc];
            }
            #pragma unroll
            for (int r = 0; r < 4; r++)
                #pragma unroll
                for (int cc = 0; cc < 4; cc++)
                    sW[(i0 + r) * SW_STRIDE + j0 + cc] = acc[r][cc];
        } else if (tid < 448) {
            const int s = tid - 384;
            float a = sv[s];
            #pragma unroll 4
            for (int p = 0; p < NS; p++) a += sV[s * SV_STRIDE + p] * sf[p];
            sh[s] = a;
        }
        __syncthreads();

        // ---- Q += F^T W ; q = c + F^T h ----
        for (int tile = tid; tile < 576; tile += NTH) {
            const int tj = tile % 24, ti = tile / 24;
            const int i0 = ti * 4, j0 = tj * 4;
            float acc[4][4];
            #pragma unroll
            for (int r = 0; r < 4; r++)
                #pragma unroll
                for (int cc = 0; cc < 4; cc++) acc[r][cc] = 0.0f;
            #pragma unroll 2
            for (int k = 0; k < NS; k++) {
                const float4 av = *(const float4*)(sF + k * NSC + i0);
                const float4 bv = *(const float4*)(sW + k * SW_STRIDE + j0);
                const float aa[4] = {av.x, av.y, av.z, av.w};
                const float bb[4] = {bv.x, bv.y, bv.z, bv.w};
                #pragma unroll
                for (int r = 0; r < 4; r++)
                    #pragma unroll
                    for (int cc = 0; cc < 4; cc++) acc[r][cc] += aa[r] * bb[cc];
            }
            #pragma unroll
            for (int r = 0; r < 4; r++)
                #pragma unroll
                for (int cc = 0; cc < 4; cc++)
                    sQ[(i0 + r) * NSC + j0 + cc] += acc[r][cc];
        }
        if (tid >= 64 && tid < 160) {
            const int j = tid - 64;
            float a = sq[j];
            #pragma unroll 4
            for (int s = 0; s < NS; s++) a += sF[s * NSC + j] * sh[s];
            sq[j] = a;
        }
        __syncthreads();

        // ---- Copy Quu into padded buffer for Cholesky ----
        for (int idx = tid; idx < NC * NC; idx += NTH) {
            const int m = idx >> 5, nn = idx & 31;
            sL[m * 33 + nn] = sQ[(NS + m) * NSC + NS + nn];
        }
        __syncthreads();

        // ---- Cholesky of Quu (warp 0, warp-synchronous right-looking) ----
        if (tid < 32) {
            #pragma unroll 1
            for (int j = 0; j < NC; j++) {
                if (lane == 0) {
                    const float d = sL[j * 33 + j];
                    const float s = sqrtf(d);
                    sL[j * 33 + j] = s;
                    sLinv[j] = 1.0f / s;
                }
                __syncwarp();
                const float invj = sLinv[j];
                float lij = 0.0f;
                if (lane > j) {
                    lij = sL[lane * 33 + j] * invj;
                    sL[lane * 33 + j] = lij;
                }
                __syncwarp();
                if (lane > j) {
                    for (int p = j + 1; p <= lane; p++)
                        sL[lane * 33 + p] -= lij * sL[p * 33 + j];
                }
                __syncwarp();
            }
        }
        __syncthreads();

        // ---- Solve Quu * Kk = -[Qux | qu], 65 RHS columns, one per thread ----
        if (tid < 65) {
            const int cidx = tid;
            float y[NC];
            #pragma unroll
            for (int i = 0; i < NC; i++) {
                float r = (cidx < NS) ? -sQ[(NS + i) * NSC + cidx] : -sq[NS + i];
                #pragma unroll
                for (int p = 0; p < i; p++) r -= sL[i * 33 + p] * y[p];
                y[i] = r * sLinv[i];
            }
            #pragma unroll
            for (int i = NC - 1; i >= 0; i--) {
                float r = y[i];
                #pragma unroll
                for (int p = i + 1; p < NC; p++) r -= sL[p * 33 + i] * y[p];
                y[i] = r * sLinv[i];
            }
            if (cidx < NS) {
                float* gk = g_K + base * (long)(NC * NS) + cidx;
                #pragma unroll
                for (int m = 0; m < NC; m++) {
                    sK[m * SK_STRIDE + cidx] = y[m];
                    gk[m * NS] = y[m];
                }
            } else {
                float* gkk = g_k + base * NC;
                #pragma unroll
                for (int m = 0; m < NC; m++) {
                    sk[m] = y[m];
                    gkk[m] = y[m];
                }
            }
        }
        __syncthreads();

        // ---- tmp = Qxx + Qxu @ K  (into sW) ; vn = qx + Qxu k (into sv) ----
        if (tid < 256) {
            const int tj = tid % 16, ti = tid / 16;
            const int i0 = ti * 4, j0 = tj * 4;
            float acc[4][4];
            #pragma unroll
            for (int r = 0; r < 4; r++)
                #pragma unroll
                for (int cc = 0; cc < 4; cc++)
                    acc[r][cc] = sQ[(i0 + r) * NSC + j0 + cc];
            #pragma unroll 2
            for (int m = 0; m < NC; m++) {
                const float4 bv = *(const float4*)(sK + m * SK_STRIDE + j0);
                const float bb[4] = {bv.x, bv.y, bv.z, bv.w};
                float aa[4];
                #pragma unroll
                for (int r = 0; r < 4; r++) aa[r] = sQ[(i0 + r) * NSC + NS + m];
                #pragma unroll
                for (int r = 0; r < 4; r++)
                    #pragma unroll
                    for (int cc = 0; cc < 4; cc++) acc[r][cc] += aa[r] * bb[cc];
            }
            #pragma unroll
            for (int r = 0; r < 4; r++)
                #pragma unroll
                for (int cc = 0; cc < 4; cc++)
                    sW[(i0 + r) * SW_STRIDE + j0 + cc] = acc[r][cc];
        } else if (tid < 320) {
            const int i = tid - 256;
            float a = sq[i];
            #pragma unroll
            for (int m = 0; m < NC; m++) a += sQ[i * NSC + NS + m] * sk[m];
            sv[i] = a;
        }
        __syncthreads();

        // ---- V = 0.5 * (tmp + tmp^T) ----
        for (int idx = tid; idx < NS * NS; idx += NTH) {
            const int i = idx >> 6, j = idx & 63;
            sV[i * SV_STRIDE + j] =
                0.5f * (sW[i * SW_STRIDE + j] + sW[j * SW_STRIDE + i]);
        }
        __syncthreads();
    }

    // ================= Forward rollout =================
    if (tid < NS) sx[tid] = gx0[b * NS + tid];
    __syncthreads();

    for (int t = 0; t < TT; t++) {
        const long base = (long)(t * BB + b);
        {
            const float4* Fg = (const float4*)(gF + base * (long)(NS * NSC));
            float4* Fd = (float4*)sF;
            for (int i = tid; i < (NS * NSC) / 4; i += NTH) Fd[i] = Fg[i];
            const float* Kg = g_K + base * (long)(NC * NS);
            for (int idx = tid; idx < NC * NS; idx += NTH)
                sK[(idx >> 6) * SK_STRIDE + (idx & 63)] = Kg[idx];
            if (tid < NS) sf[tid] = gf[base * NS + tid];
            if (tid < NC) sk[tid] = g_k[base * NC + tid];
            if (tid < NS) stau[tid] = sx[tid];
        }
        __syncthreads();

        // u[m] = K[m,:] x + k[m]   (2 rows per warp, warp-reduce)
        {
            #pragma unroll
            for (int mm = 0; mm < 2; mm++) {
                const int m = warp * 2 + mm;
                float p = sK[m * SK_STRIDE + lane] * stau[lane]
                        + sK[m * SK_STRIDE + 32 + lane] * stau[32 + lane];
                #pragma unroll
                for (int off = 16; off > 0; off >>= 1)
                    p += __shfl_xor_sync(0xffffffffu, p, off);
                if (lane == 0) stau[NS + m] = p + sk[m];
            }
        }
        __syncthreads();

        // tau out ; x = F tau + f   (4 rows per warp, warp-reduce)
        if (tid < NSC) gout[base * NSC + tid] = stau[tid];
        {
            #pragma unroll
            for (int ss = 0; ss < 4; ss++) {
                const int s = warp * 4 + ss;
                float p = 0.0f;
                #pragma unroll
                for (int q = 0; q < 3; q++)
                    p += sF[s * NSC + lane + 32 * q] * stau[lane + 32 * q];
                #pragma unroll
                for (int off = 16; off > 0; off >>= 1)
                    p += __shfl_xor_sync(0xffffffffu, p, off);
                if (lane == 0) sx[s] = p + sf[s];
            }
        }
        __syncthreads();
    }
}

extern "C" void kernel_launch(void* const* d_in, const int* in_sizes, int n_in,
                              void* d_out, int out_size)
{
    const float* gC  = (const float*)d_in[0];
    const float* gc  = (const float*)d_in[1];
    const float* gF  = (const float*)d_in[2];
    const float* gf  = (const float*)d_in[3];
    const float* gx0 = (const float*)d_in[4];
    float* gout = (float*)d_out;

    const int smem_floats =
        NS * SV_STRIDE + NS * NSC + NS * SW_STRIDE + NSC * NSC +
        NC * 33 + NC + NC * SK_STRIDE + NSC + NS + NS + NS + NC + NS + NSC;
    const int smem_bytes = smem_floats * (int)sizeof(float);

    cudaFuncSetAttribute(lqr_kernel,
                         cudaFuncAttributeMaxDynamicSharedMemorySize, smem_bytes);
    lqr_kernel<<<BB, NTH, smem_bytes>>>(gC, gc, gF, gf, gx0, gout);
}

// round 2
// speedup vs baseline: 1.6004x; 1.6004x over previous
#include <cuda_runtime.h>
#include <cstdint>

#define TT  64
#define BB  128
#define NS  64
#define NC  32
#define NSC 96
#define NTH 512
#define FULLMASK 0xffffffffu

#define SV_STRIDE 68   // 64 + 4 pad
#define SW_STRIDE 100  // 96 + 4 pad
#define SK_STRIDE 68

// Gains produced by backward pass, consumed by forward rollout.
__device__ float g_K[TT * BB * NC * NS];   // [t][b][m][i]
__device__ float g_k[TT * BB * NC];        // [t][b][m]

__device__ __forceinline__ void cp16(float4* s, const float4* g) {
    uint32_t sa = (uint32_t)__cvta_generic_to_shared(s);
    asm volatile("cp.async.cg.shared.global [%0], [%1], 16;" :: "r"(sa), "l"(g));
}
__device__ __forceinline__ void cp_commit() {
    asm volatile("cp.async.commit_group;");
}
__device__ __forceinline__ void cp_wait0() {
    asm volatile("cp.async.wait_group 0;" ::: "memory");
}

static __global__ void __launch_bounds__(NTH, 1)
lqr_kernel(const float* __restrict__ gC, const float* __restrict__ gc,
           const float* __restrict__ gF, const float* __restrict__ gf,
           const float* __restrict__ gx0, float* __restrict__ gout)
{
    extern __shared__ float sm[];
    float* sC0   = sm;                       // 9216  (double-buffered C / Q workspace; K buf in rollout)
    float* sC1   = sC0 + NSC * NSC;          // 9216
    float* sF0   = sC1 + NSC * NSC;          // 6144
    float* sF1   = sF0 + NS * NSC;           // 6144
    float* sV    = sF1 + NS * NSC;           // 64*68
    float* sW    = sV + NS * SV_STRIDE;      // 64*100  (W, later P)
    float* sL    = sW + NS * SW_STRIDE;      // 32*33
    float* sLinv = sL + NC * 33;             // 32
    float* sK    = sLinv + NC;               // 32*68
    float* sc0   = sK + NC * SK_STRIDE;      // 96
    float* sc1   = sc0 + NSC;                // 96
    float* sf0   = sc1 + NSC;                // 64
    float* sf1   = sf0 + NS;                 // 64
    float* sk0   = sf1 + NS;                 // 32 (rollout k)
    float* sk1   = sk0 + NC;                 // 32
    float* sq    = sk1 + NC;                 // 96
    float* sv    = sq + NSC;                 // 64
    float* sh    = sv + NS;                  // 64
    float* skv   = sh + NS;                  // 32 (backward k vec)
    float* sx    = skv + NC;                 // 64
    float* stau  = sx + NS;                  // 96

    const int tid  = threadIdx.x;
    const int b    = blockIdx.x;
    const int lane = tid & 31;
    const int warp = tid >> 5;

    // ---- precompute per-thread tile maps (constant over t) ----
    // P1: W = V@F, 16x24 grid of 4x4 tiles, tid < 384
    const int i0_1 = (tid / 24) * 4;
    const int j0_1 = (tid % 24) * 4;
    // P2: lower-triangle 4x4 tiles of Q (24x24 blocks, ti>=tj): 300 tiles
    int ti2 = 0, tj2 = 0;
    if (tid < 300) {
        int r = tid, t = 0;
        while (r > t) { r -= t + 1; t++; }
        ti2 = t; tj2 = r;
    }
    const int i0_2 = ti2 * 4, j0_2 = tj2 * 4;
    // P5: P = Qxu @ K, 16x32 grid of 4x2 tiles (512 tiles)
    const int i0_5 = (tid >> 5) * 4;
    const int j0_5 = (tid & 31) * 2;

    // ---- pre-issue loads for t = TT-1 (buffer parity 1) ----
    {
        const long base = (long)((TT - 1) * BB + b);
        const float4* Cg = (const float4*)(gC + base * (long)(NSC * NSC));
        const float4* Fg = (const float4*)(gF + base * (long)(NS * NSC));
        const float4* cg = (const float4*)(gc + base * NSC);
        const float4* fg = (const float4*)(gf + base * NS);
        for (int i = tid; i < (NSC * NSC) / 4; i += NTH) cp16((float4*)sC1 + i, Cg + i);
        for (int i = tid; i < (NS * NSC) / 4; i += NTH)  cp16((float4*)sF1 + i, Fg + i);
        if (tid < NSC / 4) cp16((float4*)sc1 + tid, cg + tid);
        if (tid < NS / 4)  cp16((float4*)sf1 + tid, fg + tid);
        cp_commit();
    }

    // V = 0, v = 0
    for (int i = tid; i < NS * SV_STRIDE; i += NTH) sV[i] = 0.0f;
    if (tid < NS) sv[tid] = 0.0f;

    // ================= Backward Riccati pass =================
    for (int t = TT - 1; t >= 0; --t) {
        const long base = (long)(t * BB + b);
        float* sQ  = (t & 1) ? sC1 : sC0;
        float* sF  = (t & 1) ? sF1 : sF0;
        float* scv = (t & 1) ? sc1 : sc0;
        float* sfv = (t & 1) ? sf1 : sf0;

        cp_wait0();
        __syncthreads();   // current-step data visible; prev-step phases done

        // issue prefetch for t-1 into the other buffers
        if (t > 0) {
            const long nb = base - BB;
            float* Cn = (t & 1) ? sC0 : sC1;
            float* Fn = (t & 1) ? sF0 : sF1;
            float* cn = (t & 1) ? sc0 : sc1;
            float* fn = (t & 1) ? sf0 : sf1;
            const float4* Cg = (const float4*)(gC + nb * (long)(NSC * NSC));
            const float4* Fg = (const float4*)(gF + nb * (long)(NS * NSC));
            const float4* cg = (const float4*)(gc + nb * NSC);
            const float4* fg = (const float4*)(gf + nb * NS);
            for (int i = tid; i < (NSC * NSC) / 4; i += NTH) cp16((float4*)Cn + i, Cg + i);
            for (int i = tid; i < (NS * NSC) / 4; i += NTH)  cp16((float4*)Fn + i, Fg + i);
            if (tid < NSC / 4) cp16((float4*)cn + tid, cg + tid);
            if (tid < NS / 4)  cp16((float4*)fn + tid, fg + tid);
            cp_commit();
        }

        // ---- P1: W = V @ F (V symmetric) ; h = v + V f ----
        if (tid < 384) {
            float acc[4][4];
            #pragma unroll
            for (int r = 0; r < 4; r++)
                #pragma unroll
                for (int cc = 0; cc < 4; cc++) acc[r][cc] = 0.0f;
            #pragma unroll 2
            for (int k = 0; k < NS; k++) {
                const float4 av = *(const float4*)(sV + k * SV_STRIDE + i0_1);
                const float4 bv = *(const float4*)(sF + k * NSC + j0_1);
                const float aa[4] = {av.x, av.y, av.z, av.w};
                const float bb[4] = {bv.x, bv.y, bv.z, bv.w};
                #pragma unroll
                for (int r = 0; r < 4; r++)
                    #pragma unroll
                    for (int cc = 0; cc < 4; cc++) acc[r][cc] += aa[r] * bb[cc];
            }
            #pragma unroll
            for (int r = 0; r < 4; r++)
                #pragma unroll
                for (int cc = 0; cc < 4; cc++)
                    sW[(i0_1 + r) * SW_STRIDE + j0_1 + cc] = acc[r][cc];
        } else if (tid < 448) {
            const int s = tid - 384;
            float a = sv[s];
            #pragma unroll 4
            for (int p = 0; p < NS; p++) a += sV[p * SV_STRIDE + s] * sfv[p];  // V sym
            sh[s] = a;
        }
        __syncthreads();

        // ---- P2: Q(lower) = C + F^T W ; q = c + F^T h ----
        if (tid < 300) {
            float acc[4][4];
            #pragma unroll
            for (int r = 0; r < 4; r++)
                #pragma unroll
                for (int cc = 0; cc < 4; cc++)
                    acc[r][cc] = sQ[(i0_2 + r) * NSC + j0_2 + cc];   // C (in place)
            #pragma unroll 2
            for (int k = 0; k < NS; k++) {
                const float4 av = *(const float4*)(sF + k * NSC + i0_2);
                const float4 bv = *(const float4*)(sW + k * SW_STRIDE + j0_2);
                const float aa[4] = {av.x, av.y, av.z, av.w};
                const float bb[4] = {bv.x, bv.y, bv.z, bv.w};
                #pragma unroll
                for (int r = 0; r < 4; r++)
                    #pragma unroll
                    for (int cc = 0; cc < 4; cc++) acc[r][cc] += aa[r] * bb[cc];
            }
            #pragma unroll
            for (int r = 0; r < 4; r++)
                #pragma unroll
                for (int cc = 0; cc < 4; cc++)
                    sQ[(i0_2 + r) * NSC + j0_2 + cc] = acc[r][cc];
        } else if (tid < 396) {
            const int j = tid - 300;
            float a = scv[j];
            #pragma unroll 4
            for (int s = 0; s < NS; s++) a += sF[s * NSC + j] * sh[s];
            sq[j] = a;
        }
        __syncthreads();

        // ---- P3: Cholesky of Quu in registers (warp 0, shfl-based) ----
        if (tid < 32) {
            float a[NC];
            #pragma unroll
            for (int p = 0; p < NC; p++)
                a[p] = (p <= lane) ? sQ[(NS + lane) * NSC + NS + p] : 0.0f;
            #pragma unroll
            for (int j = 0; j < NC; j++) {
                const float dj = __shfl_sync(FULLMASK, a[j], j);
                const float rinv = rsqrtf(dj);
                const float lij = a[j] * rinv;        // L[lane][j] for lane >= j
                if (lane >= j) sL[lane * 33 + j] = lij;
                if (lane == j) sLinv[j] = rinv;
                #pragma unroll
                for (int p = j + 1; p < NC; p++) {
                    const float v = __shfl_sync(FULLMASK, lij, p);  // L[p][j]
                    if (p <= lane) a[p] -= lij * v;
                }
            }
        }
        __syncthreads();

        // ---- P4: solve Quu * Kk = -[Qux | qu] (65 cols), write K/k ----
        if (tid < 65) {
            const int c = tid;
            float y[NC];
            #pragma unroll
            for (int i = 0; i < NC; i++) {
                float r0 = (c < NS) ? -sQ[(NS + i) * NSC + c] : -sq[NS + i];
                float r1 = 0.0f;
                #pragma unroll
                for (int p = 0; p < i; p++) {
                    const float lp = sL[i * 33 + p];
                    if (p & 1) r1 -= lp * y[p]; else r0 -= lp * y[p];
                }
                y[i] = (r0 + r1) * sLinv[i];
            }
            #pragma unroll
            for (int i = NC - 1; i >= 0; i--) {
                float r0 = y[i], r1 = 0.0f;
                #pragma unroll
                for (int p = i + 1; p < NC; p++) {
                    const float lp = sL[p * 33 + i];
                    if (p & 1) r1 -= lp * y[p]; else r0 -= lp * y[p];
                }
                y[i] = (r0 + r1) * sLinv[i];
            }
            if (c < NS) {
                float* gk = g_K + base * (long)(NC * NS) + c;
                #pragma unroll
                for (int m = 0; m < NC; m++) {
                    sK[m * SK_STRIDE + c] = y[m];
                    gk[m * NS] = y[m];
                }
            } else {
                float* gkk = g_k + base * NC;
                #pragma unroll
                for (int m = 0; m < NC; m++) {
                    skv[m] = y[m];
                    gkk[m] = y[m];
                }
            }
        }
        __syncthreads();

        // ---- P5: P = Qxu @ K  (Qxu read as Qux^T from lower tri), 4x2 tiles ----
        {
            float acc[4][2];
            #pragma unroll
            for (int r = 0; r < 4; r++) { acc[r][0] = 0.0f; acc[r][1] = 0.0f; }
            #pragma unroll 4
            for (int m = 0; m < NC; m++) {
                const float2 bk = *(const float2*)(sK + m * SK_STRIDE + j0_5);
                const float* qr = sQ + (NS + m) * NSC + i0_5;   // Qux row m (warp-broadcast)
                #pragma unroll
                for (int r = 0; r < 4; r++) {
                    const float a = qr[r];
                    acc[r][0] += a * bk.x;
                    acc[r][1] += a * bk.y;
                }
            }
            #pragma unroll
            for (int r = 0; r < 4; r++) {
                sW[(i0_5 + r) * SW_STRIDE + j0_5]     = acc[r][0];
                sW[(i0_5 + r) * SW_STRIDE + j0_5 + 1] = acc[r][1];
            }
        }
        __syncthreads();

        // ---- P6: V = sym(Qxx) + 0.5(P + P^T) ; vn = qx + Qxu k ----
        for (int idx = tid; idx < NS * NS; idx += NTH) {
            const int i = idx >> 6, j = idx & 63;
            const float qxx = (j <= i) ? sQ[i * NSC + j] : sQ[j * NSC + i];
            sV[i * SV_STRIDE + j] =
                qxx + 0.5f * (sW[i * SW_STRIDE + j] + sW[j * SW_STRIDE + i]);
        }
        if (tid < NS) {
            float a = sq[tid];
            #pragma unroll 4
            for (int m = 0; m < NC; m++) a += sQ[(NS + m) * NSC + tid] * skv[m];
            sv[tid] = a;
        }
        __syncthreads();
    }

    // ================= Forward rollout (double-buffered) =================
    if (tid < NS) sx[tid] = gx0[b * NS + tid];
    {   // pre-issue t = 0 (parity 0): F->sF0, K->sC0, f->sf0, k->sk0
        const long base = (long)b;
        const float4* Fg = (const float4*)(gF + base * (long)(NS * NSC));
        const float4* Kg = (const float4*)(g_K + base * (long)(NC * NS));
        const float4* fg = (const float4*)(gf + base * NS);
        const float4* kg = (const float4*)(g_k + base * NC);
        for (int i = tid; i < (NS * NSC) / 4; i += NTH) cp16((float4*)sF0 + i, Fg + i);
        for (int i = tid; i < (NC * NS) / 4; i += NTH)  cp16((float4*)sC0 + i, Kg + i);
        if (tid < NS / 4) cp16((float4*)sf0 + tid, fg + tid);
        if (tid < NC / 4) cp16((float4*)sk0 + tid, kg + tid);
        cp_commit();
    }
    __syncthreads();

    for (int t = 0; t < TT; t++) {
        const long base = (long)(t * BB + b);
        float* sFc = (t & 1) ? sF1 : sF0;
        float* sKc = (t & 1) ? sC1 : sC0;   // K stored [m][i], stride NS
        float* sfc = (t & 1) ? sf1 : sf0;
        float* skc = (t & 1) ? sk1 : sk0;

        cp_wait0();
        __syncthreads();

        if (t + 1 < TT) {
            const long nb = base + BB;
            float* Fn = (t & 1) ? sF0 : sF1;
            float* Kn = (t & 1) ? sC0 : sC1;
            float* fn = (t & 1) ? sf0 : sf1;
            float* kn = (t & 1) ? sk0 : sk1;
            const float4* Fg = (const float4*)(gF + nb * (long)(NS * NSC));
            const float4* Kg = (const float4*)(g_K + nb * (long)(NC * NS));
            const float4* fg = (const float4*)(gf + nb * NS);
            const float4* kg = (const float4*)(g_k + nb * NC);
            for (int i = tid; i < (NS * NSC) / 4; i += NTH) cp16((float4*)Fn + i, Fg + i);
            for (int i = tid; i < (NC * NS) / 4; i += NTH)  cp16((float4*)Kn + i, Kg + i);
            if (tid < NS / 4) cp16((float4*)fn + tid, fg + tid);
            if (tid < NC / 4) cp16((float4*)kn + tid, kg + tid);
            cp_commit();
        }

        // u[m] = K[m,:] x + k[m]  (2 rows per warp)
        #pragma unroll
        for (int mm = 0; mm < 2; mm++) {
            const int m = warp * 2 + mm;
            float p = sKc[m * NS + lane] * sx[lane]
                    + sKc[m * NS + 32 + lane] * sx[32 + lane];
            #pragma unroll
            for (int off = 16; off > 0; off >>= 1)
                p += __shfl_xor_sync(FULLMASK, p, off);
            if (lane == 0) stau[NS + m] = p + skc[m];
        }
        if (tid < NS) stau[tid] = sx[tid];
        __syncthreads();

        // write tau ; x_next = F tau + f  (4 rows per warp)
        if (tid < NSC) gout[base * NSC + tid] = stau[tid];
        #pragma unroll
        for (int ss = 0; ss < 4; ss++) {
            const int s = warp * 4 + ss;
            float p = 0.0f;
            #pragma unroll
            for (int q = 0; q < 3; q++)
                p += sFc[s * NSC + lane + 32 * q] * stau[lane + 32 * q];
            #pragma unroll
            for (int off = 16; off > 0; off >>= 1)
                p += __shfl_xor_sync(FULLMASK, p, off);
            if (lane == 0) sx[s] = p + sfc[s];
        }
        __syncthreads();
    }
}

extern "C" void kernel_launch(void* const* d_in, const int* in_sizes, int n_in,
                              void* d_out, int out_size)
{
    const float* gC  = (const float*)d_in[0];
    const float* gc  = (const float*)d_in[1];
    const float* gF  = (const float*)d_in[2];
    const float* gf  = (const float*)d_in[3];
    const float* gx0 = (const float*)d_in[4];
    float* gout = (float*)d_out;

    const int smem_floats =
        2 * NSC * NSC + 2 * NS * NSC + NS * SV_STRIDE + NS * SW_STRIDE +
        NC * 33 + NC + NC * SK_STRIDE + 2 * NSC + 2 * NS + 2 * NC +
        NSC + NS + NS + NC + NS + NSC;
    const int smem_bytes = smem_floats * (int)sizeof(float);

    cudaFuncSetAttribute(lqr_kernel,
                         cudaFuncAttributeMaxDynamicSharedMemorySize, smem_bytes);
    lqr_kernel<<<BB, NTH, smem_bytes>>>(gC, gc, gF, gf, gx0, gout);
}

// round 3
// speedup vs baseline: 2.0490x; 1.2803x over previous
#include <cuda_runtime.h>
#include <cstdint>

#define TT  64
#define BB  128
#define NS  64
#define NC  32
#define NSC 96
#define NTH 512
#define FULLMASK 0xffffffffu

#define SV_STRIDE 68   // 64 + 4 pad
#define SW_STRIDE 100  // 96 + 4 pad
#define SK_STRIDE 68

// Gains produced by backward pass, consumed by forward rollout.
__device__ float g_K[TT * BB * NC * NS];   // [t][b][m][i]
__device__ float g_k[TT * BB * NC];        // [t][b][m]

__device__ __forceinline__ void cp16(float4* s, const float4* g) {
    uint32_t sa = (uint32_t)__cvta_generic_to_shared(s);
    asm volatile("cp.async.cg.shared.global [%0], [%1], 16;" :: "r"(sa), "l"(g));
}
__device__ __forceinline__ void cp_commit() {
    asm volatile("cp.async.commit_group;");
}
__device__ __forceinline__ void cp_wait0() {
    asm volatile("cp.async.wait_group 0;" ::: "memory");
}

__device__ __forceinline__ void tri_decode(int q, int& ti, int& tj) {
    int t = 0, r = q;
    while (r > t) { r -= t + 1; t++; }
    ti = t; tj = r;
}

// 4x4 GEMM tile: Q[i0..+3][j0..+3] = C(in place) + sum_k F[k][i0..]*W[k][j0..]
__device__ __forceinline__ void q_tile(float* sQ, const float* sF, const float* sW,
                                       int i0, int j0) {
    float acc[4][4];
    #pragma unroll
    for (int r = 0; r < 4; r++)
        #pragma unroll
        for (int cc = 0; cc < 4; cc++)
            acc[r][cc] = sQ[(i0 + r) * NSC + j0 + cc];
    #pragma unroll 2
    for (int k = 0; k < NS; k++) {
        const float4 av = *(const float4*)(sF + k * NSC + i0);
        const float4 bv = *(const float4*)(sW + k * SW_STRIDE + j0);
        const float aa[4] = {av.x, av.y, av.z, av.w};
        const float bb[4] = {bv.x, bv.y, bv.z, bv.w};
        #pragma unroll
        for (int r = 0; r < 4; r++)
            #pragma unroll
            for (int cc = 0; cc < 4; cc++) acc[r][cc] += aa[r] * bb[cc];
    }
    #pragma unroll
    for (int r = 0; r < 4; r++)
        #pragma unroll
        for (int cc = 0; cc < 4; cc++)
            sQ[(i0 + r) * NSC + j0 + cc] = acc[r][cc];
}

static __global__ void __launch_bounds__(NTH, 1)
lqr_kernel(const float* __restrict__ gC, const float* __restrict__ gc,
           const float* __restrict__ gF, const float* __restrict__ gf,
           const float* __restrict__ gx0, float* __restrict__ gout)
{
    extern __shared__ float sm[];
    float* sC0   = sm;                       // 9216 (C/Q buf parity0; K buf in rollout)
    float* sC1   = sC0 + NSC * NSC;          // 9216
    float* sF0   = sC1 + NSC * NSC;          // 6144
    float* sF1   = sF0 + NS * NSC;           // 6144
    float* sV    = sF1 + NS * NSC;           // 64*68
    float* sW    = sV + NS * SV_STRIDE;      // 64*100
    float* sL    = sW + NS * SW_STRIDE;      // 32*33
    float* sLinv = sL + NC * 33;             // 32
    float* sLi   = sLinv + NC;               // 32*33 (triangular inverse)
    float* sG    = sLi + NC * 33;            // 32*68 (intermediate of solve)
    float* sK    = sG + NC * 68;             // 32*68
    float* sc0   = sK + NC * SK_STRIDE;      // 96
    float* sc1   = sc0 + NSC;                // 96
    float* sf0   = sc1 + NSC;                // 64
    float* sf1   = sf0 + NS;                 // 64
    float* sk0   = sf1 + NS;                 // 32
    float* sk1   = sk0 + NC;                 // 32
    float* sq    = sk1 + NC;                 // 96
    float* sv    = sq + NSC;                 // 64
    float* sh    = sv + NS;                  // 64
    float* skv   = sh + NS;                  // 32
    float* sx    = skv + NC;                 // 64
    float* stau  = sx + NS;                  // 96

    const int tid  = threadIdx.x;
    const int b    = blockIdx.x;
    const int lane = tid & 31;
    const int warp = tid >> 5;

    // ---- per-thread tile maps (constant over t) ----
    // P1: W = V@F, 16x24 grid of 4x4 tiles, tid < 384
    const int i0_1 = (tid / 24) * 4;
    const int j0_1 = (tid % 24) * 4;
    // P2 main set (threads 128..391): 128 Qxu tiles + 136 Qxx lower tiles
    int p2i0 = -1, p2j0 = 0;
    if (tid >= 128 && tid < 392) {
        const int g = tid - 128;
        int ti, tj;
        if (g < 128) { ti = 16 + (g >> 4); tj = g & 15; }
        else          tri_decode(g - 128, ti, tj);
        p2i0 = ti * 4; p2j0 = tj * 4;
    }
    // P2 Quu set (threads 32..67): 36 lower tiles of Quu
    int quui0 = -1, quuj0 = 0;
    if (tid >= 32 && tid < 68) {
        int ti, tj; tri_decode(tid - 32, ti, tj);
        quui0 = (16 + ti) * 4; quuj0 = (16 + tj) * 4;
    }
    // P5: lower-triangle V tiles, 2 rows x 4 cols, 272 tiles
    int p5i0 = -1, p5j0 = 0;
    {
        int r = tid;
        for (int ti = 0; ti < 32; ti++) {
            const int c = (ti >> 1) + 1;
            if (r < c) { p5i0 = ti * 2; p5j0 = r * 4; break; }
            r -= c;
        }
        if (tid >= 272) p5i0 = -1;
    }

    // ---- pre-issue loads for t = TT-1 (buffer parity 1) ----
    {
        const long base = (long)((TT - 1) * BB + b);
        const float4* Cg = (const float4*)(gC + base * (long)(NSC * NSC));
        const float4* Fg = (const float4*)(gF + base * (long)(NS * NSC));
        const float4* cg = (const float4*)(gc + base * NSC);
        const float4* fg = (const float4*)(gf + base * NS);
        for (int i = tid; i < (NSC * NSC) / 4; i += NTH) cp16((float4*)sC1 + i, Cg + i);
        for (int i = tid; i < (NS * NSC) / 4; i += NTH)  cp16((float4*)sF1 + i, Fg + i);
        if (tid < NSC / 4) cp16((float4*)sc1 + tid, cg + tid);
        if (tid < NS / 4)  cp16((float4*)sf1 + tid, fg + tid);
        cp_commit();
    }

    // V = 0, v = 0
    for (int i = tid; i < NS * SV_STRIDE; i += NTH) sV[i] = 0.0f;
    if (tid < NS) sv[tid] = 0.0f;

    // ================= Backward Riccati pass =================
    for (int t = TT - 1; t >= 0; --t) {
        const long base = (long)(t * BB + b);
        float* sQ  = (t & 1) ? sC1 : sC0;
        float* sF  = (t & 1) ? sF1 : sF0;
        float* scv = (t & 1) ? sc1 : sc0;
        float* sfv = (t & 1) ? sf1 : sf0;

        cp_wait0();
        __syncthreads();                     // S1

        if (t > 0) {                         // prefetch t-1 into other buffers
            const long nb = base - BB;
            float* Cn = (t & 1) ? sC0 : sC1;
            float* Fn = (t & 1) ? sF0 : sF1;
            float* cn = (t & 1) ? sc0 : sc1;
            float* fn = (t & 1) ? sf0 : sf1;
            const float4* Cg = (const float4*)(gC + nb * (long)(NSC * NSC));
            const float4* Fg = (const float4*)(gF + nb * (long)(NS * NSC));
            const float4* cg = (const float4*)(gc + nb * NSC);
            const float4* fg = (const float4*)(gf + nb * NS);
            for (int i = tid; i < (NSC * NSC) / 4; i += NTH) cp16((float4*)Cn + i, Cg + i);
            for (int i = tid; i < (NS * NSC) / 4; i += NTH)  cp16((float4*)Fn + i, Fg + i);
            if (tid < NSC / 4) cp16((float4*)cn + tid, cg + tid);
            if (tid < NS / 4)  cp16((float4*)fn + tid, fg + tid);
            cp_commit();
        }

        // ---- P1: W = V @ F (V symmetric) ; h = v + V f ----
        if (tid < 384) {
            float acc[4][4];
            #pragma unroll
            for (int r = 0; r < 4; r++)
                #pragma unroll
                for (int cc = 0; cc < 4; cc++) acc[r][cc] = 0.0f;
            #pragma unroll 2
            for (int k = 0; k < NS; k++) {
                const float4 av = *(const float4*)(sV + k * SV_STRIDE + i0_1);
                const float4 bv = *(const float4*)(sF + k * NSC + j0_1);
                const float aa[4] = {av.x, av.y, av.z, av.w};
                const float bb[4] = {bv.x, bv.y, bv.z, bv.w};
                #pragma unroll
                for (int r = 0; r < 4; r++)
                    #pragma unroll
                    for (int cc = 0; cc < 4; cc++) acc[r][cc] += aa[r] * bb[cc];
            }
            #pragma unroll
            for (int r = 0; r < 4; r++)
                #pragma unroll
                for (int cc = 0; cc < 4; cc++)
                    sW[(i0_1 + r) * SW_STRIDE + j0_1 + cc] = acc[r][cc];
        } else if (tid < 448) {
            const int s = tid - 384;
            float a = sv[s];
            #pragma unroll 4
            for (int p = 0; p < NS; p++) a += sV[p * SV_STRIDE + s] * sfv[p];
            sh[s] = a;
        }
        __syncthreads();                     // S2

        // ---- P2 + overlapped Cholesky/Linv ----
        if (quui0 >= 0) q_tile(sQ, sF, sW, quui0, quuj0);   // 36 Quu tiles first
        if (tid >= 96 && tid < 128) {                       // qu (warp 3, not in bar)
            const int j = NS + (tid - 96);
            float a = scv[j];
            #pragma unroll 4
            for (int s = 0; s < NS; s++) a += sF[s * NSC + j] * sh[s];
            sq[j] = a;
        }
        if (warp < 3) asm volatile("bar.sync 1, 96;" ::: "memory");
        if (warp == 0) {
            // Cholesky of Quu in registers (shfl)
            float a[NC];
            #pragma unroll
            for (int p = 0; p < NC; p++)
                a[p] = (p <= lane) ? sQ[(NS + lane) * NSC + NS + p] : 0.0f;
            #pragma unroll
            for (int j = 0; j < NC; j++) {
                const float dj = __shfl_sync(FULLMASK, a[j], j);
                const float rinv = rsqrtf(dj);
                const float lij = a[j] * rinv;
                if (lane >= j) sL[lane * 33 + j] = lij;
                if (lane == j) sLinv[j] = rinv;
                #pragma unroll
                for (int p = j + 1; p < NC; p++) {
                    const float v = __shfl_sync(FULLMASK, lij, p);
                    if (p <= lane) a[p] -= lij * v;
                }
            }
            // Explicit triangular inverse: lane j computes column j of Linv
            float x[NC];
            #pragma unroll
            for (int i = 0; i < NC; i++) x[i] = 0.0f;
            #pragma unroll
            for (int i = 0; i < NC; i++) {
                float s = 0.0f;
                #pragma unroll
                for (int p = 0; p < i; p++) s += sL[i * 33 + p] * x[p];
                float val = (i == lane) ? sLinv[i] : (-sLinv[i] * s);
                x[i] = (i >= lane) ? val : 0.0f;
            }
            #pragma unroll
            for (int i = 0; i < NC; i++)
                if (i >= lane) sLi[i * 33 + lane] = x[i];
        }
        if (p2i0 >= 0) q_tile(sQ, sF, sW, p2i0, p2j0);      // remaining 264 tiles
        if (tid >= 392 && tid < 456) {                      // qx
            const int j = tid - 392;
            float a = scv[j];
            #pragma unroll 4
            for (int s = 0; s < NS; s++) a += sF[s * NSC + j] * sh[s];
            sq[j] = a;
        }
        __syncthreads();                     // S3

        // ---- P4a: G = -Linv @ [Qux | qu]  (parallel GEMM) ----
        {
            const int i = tid >> 4, c0 = (tid & 15) << 2;
            float a0 = 0.f, a1 = 0.f, a2 = 0.f, a3 = 0.f;
            for (int p = 0; p <= i; p++) {
                const float li = sLi[i * 33 + p];
                const float4 r = *(const float4*)(sQ + (NS + p) * NSC + c0);
                a0 -= li * r.x; a1 -= li * r.y; a2 -= li * r.z; a3 -= li * r.w;
            }
            *(float4*)(sG + i * 68 + c0) = make_float4(a0, a1, a2, a3);
            if (tid < NC) {
                const int ii = tid; float a = 0.f;
                for (int p = 0; p <= ii; p++) a -= sLi[ii * 33 + p] * sq[NS + p];
                sG[ii * 68 + 64] = a;
            }
        }
        __syncthreads();                     // S4

        // ---- P4b: K = Linv^T @ G ; write K/k to smem + gmem ----
        {
            const int m = tid >> 4, c0 = (tid & 15) << 2;
            float a0 = 0.f, a1 = 0.f, a2 = 0.f, a3 = 0.f;
            for (int i = m; i < NC; i++) {
                const float li = sLi[i * 33 + m];
                const float4 g4 = *(const float4*)(sG + i * 68 + c0);
                a0 += li * g4.x; a1 += li * g4.y; a2 += li * g4.z; a3 += li * g4.w;
            }
            const float4 kk = make_float4(a0, a1, a2, a3);
            *(float4*)(sK + m * SK_STRIDE + c0) = kk;
            *(float4*)(g_K + base * (long)(NC * NS) + m * NS + c0) = kk;
            if (tid < NC) {
                const int mm = tid; float a = 0.f;
                for (int i = mm; i < NC; i++) a += sLi[i * 33 + mm] * sG[i * 68 + 64];
                skv[mm] = a;
                g_k[base * NC + mm] = a;
            }
        }
        __syncthreads();                     // S5

        // ---- P5 (fused): V lower = Qxx + Qxu@K, mirrored ; vn = qx + Qxu k ----
        if (p5i0 >= 0) {
            const int i0 = p5i0, j0 = p5j0;
            float acc[2][4];
            #pragma unroll
            for (int r = 0; r < 2; r++)
                #pragma unroll
                for (int cc = 0; cc < 4; cc++) {
                    const int i = i0 + r, j = j0 + cc;
                    acc[r][cc] = (j <= i) ? sQ[i * NSC + j] : 0.0f;
                }
            #pragma unroll 4
            for (int m = 0; m < NC; m++) {
                const float2 qa = *(const float2*)(sQ + (NS + m) * NSC + i0);
                const float4 kb = *(const float4*)(sK + m * SK_STRIDE + j0);
                const float bb[4] = {kb.x, kb.y, kb.z, kb.w};
                #pragma unroll
                for (int cc = 0; cc < 4; cc++) {
                    acc[0][cc] += qa.x * bb[cc];
                    acc[1][cc] += qa.y * bb[cc];
                }
            }
            #pragma unroll
            for (int r = 0; r < 2; r++)
                #pragma unroll
                for (int cc = 0; cc < 4; cc++) {
                    const int i = i0 + r, j = j0 + cc;
                    if (j <= i) {
                        sV[i * SV_STRIDE + j] = acc[r][cc];
                        sV[j * SV_STRIDE + i] = acc[r][cc];
                    }
                }
        }
        if (tid >= 448) {
            const int i = tid - 448;
            float a = sq[i];
            #pragma unroll 4
            for (int m = 0; m < NC; m++) a += sQ[(NS + m) * NSC + i] * skv[m];
            sv[i] = a;
        }
        // no trailing sync: next iteration's S1 covers sV/sv visibility
    }

    __syncthreads();   // protect sC0/sF0 reuse before forward prefetch

    // ================= Forward rollout (double-buffered) =================
    if (tid < NS) sx[tid] = gx0[b * NS + tid];
    {
        const long base = (long)b;
        const float4* Fg = (const float4*)(gF + base * (long)(NS * NSC));
        const float4* Kg = (const float4*)(g_K + base * (long)(NC * NS));
        const float4* fg = (const float4*)(gf + base * NS);
        const float4* kg = (const float4*)(g_k + base * NC);
        for (int i = tid; i < (NS * NSC) / 4; i += NTH) cp16((float4*)sF0 + i, Fg + i);
        for (int i = tid; i < (NC * NS) / 4; i += NTH)  cp16((float4*)sC0 + i, Kg + i);
        if (tid < NS / 4) cp16((float4*)sf0 + tid, fg + tid);
        if (tid < NC / 4) cp16((float4*)sk0 + tid, kg + tid);
        cp_commit();
    }
    __syncthreads();

    for (int t = 0; t < TT; t++) {
        const long base = (long)(t * BB + b);
        float* sFc = (t & 1) ? sF1 : sF0;
        float* sKc = (t & 1) ? sC1 : sC0;   // K stored [m][i], stride NS
        float* sfc = (t & 1) ? sf1 : sf0;
        float* skc = (t & 1) ? sk1 : sk0;

        cp_wait0();
        __syncthreads();

        if (t + 1 < TT) {
            const long nb = base + BB;
            float* Fn = (t & 1) ? sF0 : sF1;
            float* Kn = (t & 1) ? sC0 : sC1;
            float* fn = (t & 1) ? sf0 : sf1;
            float* kn = (t & 1) ? sk0 : sk1;
            const float4* Fg = (const float4*)(gF + nb * (long)(NS * NSC));
            const float4* Kg = (const float4*)(g_K + nb * (long)(NC * NS));
            const float4* fg = (const float4*)(gf + nb * NS);
            const float4* kg = (const float4*)(g_k + nb * NC);
            for (int i = tid; i < (NS * NSC) / 4; i += NTH) cp16((float4*)Fn + i, Fg + i);
            for (int i = tid; i < (NC * NS) / 4; i += NTH)  cp16((float4*)Kn + i, Kg + i);
            if (tid < NS / 4) cp16((float4*)fn + tid, fg + tid);
            if (tid < NC / 4) cp16((float4*)kn + tid, kg + tid);
            cp_commit();
        }

        // u[m] = K[m,:] x + k[m]  (2 rows per warp)
        #pragma unroll
        for (int mm = 0; mm < 2; mm++) {
            const int m = warp * 2 + mm;
            float p = sKc[m * NS + lane] * sx[lane]
                    + sKc[m * NS + 32 + lane] * sx[32 + lane];
            #pragma unroll
            for (int off = 16; off > 0; off >>= 1)
                p += __shfl_xor_sync(FULLMASK, p, off);
            if (lane == 0) stau[NS + m] = p + skc[m];
        }
        if (tid < NS) stau[tid] = sx[tid];
        __syncthreads();

        // write tau ; x_next = F tau + f  (4 rows per warp)
        if (tid < NSC) gout[base * NSC + tid] = stau[tid];
        #pragma unroll
        for (int ss = 0; ss < 4; ss++) {
            const int s = warp * 4 + ss;
            float p = 0.0f;
            #pragma unroll
            for (int q = 0; q < 3; q++)
                p += sFc[s * NSC + lane + 32 * q] * stau[lane + 32 * q];
            #pragma unroll
            for (int off = 16; off > 0; off >>= 1)
                p += __shfl_xor_sync(FULLMASK, p, off);
            if (lane == 0) sx[s] = p + sfc[s];
        }
        __syncthreads();
    }
}

extern "C" void kernel_launch(void* const* d_in, const int* in_sizes, int n_in,
                              void* d_out, int out_size)
{
    const float* gC  = (const float*)d_in[0];
    const float* gc  = (const float*)d_in[1];
    const float* gF  = (const float*)d_in[2];
    const float* gf  = (const float*)d_in[3];
    const float* gx0 = (const float*)d_in[4];
    float* gout = (float*)d_out;

    const int smem_floats =
        2 * NSC * NSC + 2 * NS * NSC + NS * SV_STRIDE + NS * SW_STRIDE +
        NC * 33 + NC + NC * 33 + NC * 68 + NC * SK_STRIDE +
        2 * NSC + 2 * NS + 2 * NC + NSC + NS + NS + NC + NS + NSC;
    const int smem_bytes = smem_floats * (int)sizeof(float);

    cudaFuncSetAttribute(lqr_kernel,
                         cudaFuncAttributeMaxDynamicSharedMemorySize, smem_bytes);
    lqr_kernel<<<BB, NTH, smem_bytes>>>(gC, gc, gF, gf, gx0, gout);
}